// round 5
// baseline (speedup 1.0000x reference)
#include <cuda_runtime.h>
#include <math.h>

#define Bsz 32
#define Ssz 512
#define Esz 256
#define HDz 256
#define Hsz 512
#define Lsz 32
#define NG  1024   // 4*HD gate rows per direction
#define RPITCH 268 // w_s smem pitch (floats)

// smem layout for k_recur (dynamic):
//   [0,16)    full mbars (2 x u64)
//   [16,32)   empty mbars (2 x u64)
//   [64,8256) h buffers: 2 slots x 1024 floats ([b][unit], pitch 256)
//   [8256,..) w_s 128 x RPITCH floats
#define SM_HB_OFF   64
#define SM_W_OFF    8256
#define RSMEM_BYTES (SM_W_OFF + 128 * RPITCH * 4)

// ------------------- scratch -------------------
__device__ float g_x0[Bsz * Ssz * Esz];                 // embed out
__device__ float g_gx[2 * Bsz * Ssz * NG];              // gate preacts, both dirs
__device__ float g_h0[Bsz * Ssz * Hsz];                 // layer0 out
__device__ float g_h1[Bsz * Ssz * Hsz];                 // layer1 out

// ------------------- packed f32x2 helpers -------------------
__device__ __forceinline__ void dfma2(unsigned long long& d, unsigned long long a,
                                      unsigned long long b) {
    asm("fma.rn.f32x2 %0, %1, %2, %0;" : "+l"(d) : "l"(a), "l"(b));
}
__device__ __forceinline__ float2 up2(unsigned long long v) {
    float2 f;
    asm("mov.b64 {%0, %1}, %2;" : "=f"(f.x), "=f"(f.y) : "l"(v));
    return f;
}
__device__ __forceinline__ unsigned long long dupf(float b) {
    unsigned long long r;
    asm("mov.b64 %0, {%1, %1};" : "=l"(r) : "f"(b));
    return r;
}
__device__ __forceinline__ unsigned smem_u32(const void* p) {
    unsigned a;
    asm("{ .reg .u64 t; cvta.to.shared.u64 t, %1; cvt.u32.u64 %0, t; }"
        : "=r"(a) : "l"(p));
    return a;
}
__device__ __forceinline__ unsigned mapa32(unsigned addr, unsigned rank) {
    unsigned r;
    asm("mapa.shared::cluster.u32 %0, %1, %2;" : "=r"(r) : "r"(addr), "r"(rank));
    return r;
}
__device__ __forceinline__ void wait_par_acq_cluster(unsigned mbar, unsigned parity) {
    asm volatile(
        "{\n\t.reg .pred P;\n"
        "W%=:\n\t"
        "mbarrier.try_wait.parity.acquire.cluster.shared::cta.b64 P, [%0], %1, 0x989680;\n\t"
        "@P bra D%=;\n\t"
        "bra W%=;\n"
        "D%=:\n\t}"
        :: "r"(mbar), "r"(parity) : "memory");
}
__device__ __forceinline__ void st_async_f32(unsigned dst, float v, unsigned mbar) {
    asm volatile(
        "st.async.shared::cluster.mbarrier::complete_tx::bytes.b32 [%0], %1, [%2];"
        :: "r"(dst), "r"(__float_as_uint(v)), "r"(mbar) : "memory");
}

// ------------------- embed -------------------
__global__ void k_embed(const int* __restrict__ x, const float* __restrict__ emb,
                        float* __restrict__ out) {
    int row = blockIdx.x;
    int t = threadIdx.x;               // 64 threads
    int tok = x[row];
    const float4* s = (const float4*)(emb + (size_t)tok * Esz);
    ((float4*)(out + (size_t)row * Esz))[t] = s[t];
}

// ------------------- GEMM: C[M,N] = A[M,K] @ W[N,K]^T + b1 + b2 -------------------
// BM=BN=128, BK=8, 256 threads, 8x8 per thread, FMA2 packed along M
__global__ __launch_bounds__(256) void k_gemm(const float* __restrict__ A,
                                              const float* __restrict__ W,
                                              const float* __restrict__ b1,
                                              const float* __restrict__ b2,
                                              float* __restrict__ C,
                                              int K, int N) {
    __shared__ __align__(16) float As[8][132];
    __shared__ __align__(16) float Bs[8][132];
    int m0 = blockIdx.y * 128, n0 = blockIdx.x * 128;
    int tid = threadIdx.x;
    int tx = tid & 15, ty = tid >> 4;
    int lr = tid >> 1;
    int lk = (tid & 1) * 4;
    const float* Ap = A + (size_t)(m0 + lr) * K + lk;
    const float* Wp = W + (size_t)(n0 + lr) * K + lk;

    unsigned long long acc[4][8];
#pragma unroll
    for (int i = 0; i < 4; i++)
#pragma unroll
        for (int j = 0; j < 8; j++) acc[i][j] = 0ull;

    float4 av = *(const float4*)(Ap);
    float4 bv = *(const float4*)(Wp);

    for (int k0 = 0; k0 < K; k0 += 8) {
        __syncthreads();
        As[lk + 0][lr] = av.x; As[lk + 1][lr] = av.y;
        As[lk + 2][lr] = av.z; As[lk + 3][lr] = av.w;
        Bs[lk + 0][lr] = bv.x; Bs[lk + 1][lr] = bv.y;
        Bs[lk + 2][lr] = bv.z; Bs[lk + 3][lr] = bv.w;
        __syncthreads();
        float4 av_n = av, bv_n = bv;
        if (k0 + 8 < K) {
            av_n = *(const float4*)(Ap + k0 + 8);
            bv_n = *(const float4*)(Wp + k0 + 8);
        }
#pragma unroll
        for (int kk = 0; kk < 8; kk++) {
            ulonglong2 A0 = *(const ulonglong2*)&As[kk][ty * 4];
            ulonglong2 A1 = *(const ulonglong2*)&As[kk][64 + ty * 4];
            float4 q0 = *(const float4*)&Bs[kk][tx * 4];
            float4 q1 = *(const float4*)&Bs[kk][64 + tx * 4];
            unsigned long long am[4] = {A0.x, A0.y, A1.x, A1.y};
            unsigned long long bd[8] = {dupf(q0.x), dupf(q0.y), dupf(q0.z), dupf(q0.w),
                                        dupf(q1.x), dupf(q1.y), dupf(q1.z), dupf(q1.w)};
#pragma unroll
            for (int mp = 0; mp < 4; mp++)
#pragma unroll
                for (int j = 0; j < 8; j++) dfma2(acc[mp][j], am[mp], bd[j]);
        }
        av = av_n; bv = bv_n;
    }

#pragma unroll
    for (int mp = 0; mp < 4; mp++) {
        int r = m0 + ((mp < 2) ? ty * 4 + 2 * mp : 64 + ty * 4 + 2 * (mp - 2));
#pragma unroll
        for (int j = 0; j < 8; j++) {
            int c = n0 + ((j < 4) ? 4 * tx + j : 64 + 4 * tx + (j - 4));
            float2 f = up2(acc[mp][j]);
            float bb = b1[c] + b2[c];
            C[(size_t)r * N + c]       = f.x + bb;
            C[(size_t)(r + 1) * N + c] = f.y + bb;
        }
    }
}

__device__ __forceinline__ float sigm(float x) { return 1.f / (1.f + expf(-x)); }

// ------------------- BiLSTM recurrence: DSMEM push + mbarrier exchange -------------------
// grid (8, 16): x = unit-slice (cluster dim 8), y = dir*8 + bgroup. 256 threads.
__global__ __launch_bounds__(256) __cluster_dims__(8, 1, 1)
void k_recur(const float* __restrict__ gx, const float* __restrict__ w_hh,
             const int* __restrict__ xlen, float* __restrict__ hout) {
    extern __shared__ __align__(16) char smraw[];
    float* hbuf = (float*)(smraw + SM_HB_OFF);      // 2 x 1024 floats
    float* w_s  = (float*)(smraw + SM_W_OFF);       // 128 x RPITCH
    unsigned mb_full  = smem_u32(smraw);            // full[0]@+0, full[1]@+8
    unsigned mb_empty = mb_full + 16;               // empty[0]@+16, empty[1]@+24
    unsigned hb_u32   = smem_u32(hbuf);

    int us  = blockIdx.x;
    int dir = blockIdx.y >> 3;
    int bg  = blockIdx.y & 7;
    int U0 = us * 32, B0 = bg * 4;
    int t = threadIdx.x;
    int col = t >> 1, bp = t & 1;
    int b0 = 2 * bp, b1 = 2 * bp + 1;
    int grow = (col & 3) * 256 + U0 + (col >> 2);

    const float* wd  = w_hh + (size_t)dir * NG * HDz;
    const float* gxd = gx + (size_t)dir * ((size_t)Bsz * Ssz * NG);

    // init mbars + zero slot0
    if (t == 0) {
        asm volatile("mbarrier.init.shared.b64 [%0], 1;" :: "r"(mb_full) : "memory");
        asm volatile("mbarrier.init.shared.b64 [%0], 1;" :: "r"(mb_full + 8) : "memory");
        asm volatile("mbarrier.init.shared.b64 [%0], 8;" :: "r"(mb_empty) : "memory");
        asm volatile("mbarrier.init.shared.b64 [%0], 8;" :: "r"(mb_empty + 8) : "memory");
    }
    for (int idx = t; idx < 1024; idx += 256) hbuf[idx] = 0.f;

    // load w slice: w_s[c][k] = w_hh[gate*256 + U0 + ul][k]
    for (int idx = t; idx < 128 * 256; idx += 256) {
        int c = idx >> 8, k = idx & 255;
        int gr = (c & 3) * 256 + U0 + (c >> 2);
        w_s[c * RPITCH + k] = wd[(size_t)gr * HDz + k];
    }

    int lenA = xlen[B0 + b0], lenB = xlen[B0 + b1];
    float c0s = 0.f, h0s = 0.f, c1s = 0.f, h1s = 0.f;
    __syncthreads();
    // peers' mbar inits must be visible before first st.async / remote arrive
    asm volatile("barrier.cluster.arrive.aligned;" ::: "memory");
    asm volatile("barrier.cluster.wait.aligned;" ::: "memory");

    const float* wp = w_s + col * RPITCH;
    bool g0lane = (t & 6) == 0;
    int U = U0 + (t >> 3);

    // precompute peer addresses (used by g0lanes / tid<8)
    unsigned peer_hb[8], peer_full[8];
#pragma unroll
    for (int r = 0; r < 8; r++) {
        peer_hb[r]   = mapa32(hb_u32, r);
        peer_full[r] = mapa32(mb_full, r);
    }

    int fu0 = 0, fu1 = 0, eu0 = 0, eu1 = 0;

    for (int step = 0; step < 512; step++) {
        int si = step & 1;
        int so = si ^ 1;
        if (step >= 1) {
            // wait h inputs delivered
            if (si == 0) { wait_par_acq_cluster(mb_full, fu0 & 1); fu0++; }
            else         { wait_par_acq_cluster(mb_full + 8, fu1 & 1); fu1++; }
            // wait output slot free (consumers of step-1 done)
            if (so == 0) { wait_par_acq_cluster(mb_empty, eu0 & 1); eu0++; }
            else         { wait_par_acq_cluster(mb_empty + 8, eu1 & 1); eu1++; }
        }
        if (step <= 510 && t == 0) {
            asm volatile(
                "mbarrier.arrive.expect_tx.release.cluster.shared::cta.b64 _, [%0], %1;"
                :: "r"(mb_full + so * 8), "r"(4096u) : "memory");
        }

        int sA = step, sB = step;
        if (dir) {
            sA = (step < lenA) ? (lenA - 1 - step) : step;
            sB = (step < lenB) ? (lenB - 1 - step) : step;
        }
        float gA = __ldg(gxd + ((size_t)(B0 + b0) * Ssz + sA) * NG + grow);
        float gB = __ldg(gxd + ((size_t)(B0 + b1) * Ssz + sB) * NG + grow);

        const float* hap = hbuf + si * 1024 + b0 * 256;
        const float* hbp = hbuf + si * 1024 + b1 * 256;
        unsigned long long ac0a = 0, ac0b = 0, ac1a = 0, ac1b = 0;
#pragma unroll 8
        for (int kq = 0; kq < 64; kq++) {
            ulonglong2 w2 = *(const ulonglong2*)(wp + kq * 4);
            ulonglong2 hA = *(const ulonglong2*)(hap + kq * 4);
            ulonglong2 hB = *(const ulonglong2*)(hbp + kq * 4);
            dfma2(ac0a, w2.x, hA.x); dfma2(ac0b, w2.y, hA.y);
            dfma2(ac1a, w2.x, hB.x); dfma2(ac1b, w2.y, hB.y);
        }
        float2 u;
        u = up2(ac0a); float a0 = u.x + u.y;
        u = up2(ac0b); a0 += u.x + u.y; a0 += gA;
        u = up2(ac1a); float a1 = u.x + u.y;
        u = up2(ac1b); a1 += u.x + u.y; a1 += gB;

        // gather gates f,g,o from cols +1,+2,+3 (lanes +2,+4,+6)
        float fA = __shfl_down_sync(0xffffffffu, a0, 2);
        float gGA = __shfl_down_sync(0xffffffffu, a0, 4);
        float oA = __shfl_down_sync(0xffffffffu, a0, 6);
        float fB = __shfl_down_sync(0xffffffffu, a1, 2);
        float gGB = __shfl_down_sync(0xffffffffu, a1, 4);
        float oB = __shfl_down_sync(0xffffffffu, a1, 6);

        if (g0lane) {
            float iv = sigm(a0), fv = sigm(fA), gv = tanhf(gGA), ov = sigm(oA);
            float cn = fv * c0s + iv * gv;
            float hn = ov * tanhf(cn);
            bool m = step < lenA;
            c0s = m ? cn : c0s; h0s = m ? hn : h0s;
            float out0 = m ? hn : 0.f;

            iv = sigm(a1); fv = sigm(fB); gv = tanhf(gGB); ov = sigm(oB);
            cn = fv * c1s + iv * gv;
            hn = ov * tanhf(cn);
            bool m2 = step < lenB;
            c1s = m2 ? cn : c1s; h1s = m2 ? hn : h1s;
            float out1 = m2 ? hn : 0.f;

            if (step <= 510) {
                unsigned o0 = (unsigned)((so << 10) + b0 * 256 + U) * 4u;
                unsigned o1 = (unsigned)((so << 10) + b1 * 256 + U) * 4u;
#pragma unroll
                for (int r = 0; r < 8; r++) {
                    unsigned mb = peer_full[r] + so * 8;
                    st_async_f32(peer_hb[r] + o0, h0s, mb);
                    st_async_f32(peer_hb[r] + o1, h1s, mb);
                }
            }

            int posA, posB, oc;
            if (!dir) { posA = step; posB = step; oc = U; }
            else {
                posA = m  ? (lenA - 1 - step) : step;
                posB = m2 ? (lenB - 1 - step) : step;
                oc = 256 + U;
            }
            hout[((size_t)(B0 + b0) * Ssz + posA) * Hsz + oc] = out0;
            hout[((size_t)(B0 + b1) * Ssz + posB) * Hsz + oc] = out1;
        }

        if (step == 511) break;
        __syncthreads();   // all reads of hbuf[si] complete
        if (t < 8) {
            unsigned ea = mapa32(mb_empty + si * 8, (unsigned)t);
            asm volatile(
                "mbarrier.arrive.release.cluster.shared::cluster.b64 _, [%0];"
                :: "r"(ea) : "memory");
        }
    }
}

// ------------------- emissions: out[M,32] = h[M,512] @ dw[32,512]^T + db -------------------
__global__ __launch_bounds__(256) void k_emis(const float* __restrict__ h,
                                              const float* __restrict__ dw,
                                              const float* __restrict__ db,
                                              float* __restrict__ out) {
    __shared__ float wT[128 * 33];
    __shared__ float hs[32 * 128];
    int tid = threadIdx.x;
    int w = tid >> 5, j = tid & 31;
    int row0 = blockIdx.x * 32;
    float acc[4] = {0.f, 0.f, 0.f, 0.f};
    for (int kc = 0; kc < 4; kc++) {
        __syncthreads();
        for (int idx = tid; idx < 4096; idx += 256) {
            int jj = idx >> 7, k = idx & 127;
            wT[k * 33 + jj] = dw[(size_t)jj * 512 + kc * 128 + k];
        }
        for (int idx = tid; idx < 4096; idx += 256) {
            int r = idx >> 7, k = idx & 127;
            hs[r * 128 + k] = h[(size_t)(row0 + r) * 512 + kc * 128 + k];
        }
        __syncthreads();
#pragma unroll 4
        for (int k = 0; k < 128; k++) {
            float wv = wT[k * 33 + j];
#pragma unroll
            for (int i = 0; i < 4; i++) acc[i] += hs[(w * 4 + i) * 128 + k] * wv;
        }
    }
    float bias = db[j];
#pragma unroll
    for (int i = 0; i < 4; i++)
        out[(size_t)(row0 + w * 4 + i) * 32 + j] = acc[i] + bias;
}

// ------------------- Viterbi: 32 blocks x 32 threads -------------------
__global__ void k_viterbi(const float* __restrict__ em, const int* __restrict__ xlen,
                          const float* __restrict__ trans, const float* __restrict__ st,
                          const float* __restrict__ et,
                          float* __restrict__ tags_out, float* __restrict__ scores_out) {
    __shared__ unsigned char bp[512][32];
    int b = blockIdx.x, j = threadIdx.x;
    int len = xlen[b];
    float tc[32];
#pragma unroll
    for (int i = 0; i < 32; i++) tc[i] = trans[i * 32 + j];
    const float* e = em + (size_t)b * Ssz * Lsz;
    float alpha = st[j] + e[j];
    for (int t = 1; t < 512; t++) {
        if (t < len) {
            float best = -1e30f; int arg = 0;
#pragma unroll
            for (int i = 0; i < 32; i++) {
                float ai = __shfl_sync(0xffffffffu, alpha, i);
                float cand = ai + tc[i];
                if (cand > best) { best = cand; arg = i; }
            }
            alpha = best + e[(size_t)t * 32 + j];
            bp[t][j] = (unsigned char)arg;
        } else {
            bp[t][j] = (unsigned char)j;
        }
    }
    __syncwarp();
    float fin = alpha + et[j];
    float bv = fin; int bi = j;
#pragma unroll
    for (int off = 16; off; off >>= 1) {
        float ovv = __shfl_down_sync(0xffffffffu, bv, off);
        int oi = __shfl_down_sync(0xffffffffu, bi, off);
        if (ovv > bv || (ovv == bv && oi < bi)) { bv = ovv; bi = oi; }
    }
    if (j == 0) {
        scores_out[b] = bv;
        int tg = bi;
        for (int t = 511; t >= 1; t--) {
            tags_out[(size_t)b * Ssz + t] = (t < len) ? (float)tg : 0.f;
            tg = bp[t][tg];
        }
        tags_out[(size_t)b * Ssz] = (float)tg;
    }
}

// ------------------- launch -------------------
extern "C" void kernel_launch(void* const* d_in, const int* in_sizes, int n_in,
                              void* d_out, int out_size) {
    const int*   x       = (const int*)d_in[0];
    const int*   xlen    = (const int*)d_in[1];
    const float* emb     = (const float*)d_in[2];
    const float* w_ih_l0 = (const float*)d_in[3];
    const float* w_hh_l0 = (const float*)d_in[4];
    const float* b_ih_l0 = (const float*)d_in[5];
    const float* b_hh_l0 = (const float*)d_in[6];
    const float* w_ih_l1 = (const float*)d_in[7];
    const float* w_hh_l1 = (const float*)d_in[8];
    const float* b_ih_l1 = (const float*)d_in[9];
    const float* b_hh_l1 = (const float*)d_in[10];
    const float* dw      = (const float*)d_in[11];
    const float* db      = (const float*)d_in[12];
    const float* trans   = (const float*)d_in[13];
    const float* strn    = (const float*)d_in[14];
    const float* etrn    = (const float*)d_in[15];
    float* out = (float*)d_out;

    float *x0, *gx, *h0, *h1;
    cudaGetSymbolAddress((void**)&x0, g_x0);
    cudaGetSymbolAddress((void**)&gx, g_gx);
    cudaGetSymbolAddress((void**)&h0, g_h0);
    cudaGetSymbolAddress((void**)&h1, g_h1);

    const size_t GXD = (size_t)Bsz * Ssz * NG;
    cudaFuncSetAttribute(k_recur, cudaFuncAttributeMaxDynamicSharedMemorySize, RSMEM_BYTES);

    k_embed<<<Bsz * Ssz, 64>>>(x, emb, x0);

    // layer 0: K=256
    k_gemm<<<dim3(8, 128), 256>>>(x0, w_ih_l0,            b_ih_l0,      b_hh_l0,      gx,       256, NG);
    k_gemm<<<dim3(8, 128), 256>>>(x0, w_ih_l0 + NG * 256, b_ih_l0 + NG, b_hh_l0 + NG, gx + GXD, 256, NG);
    k_recur<<<dim3(8, 16), 256, RSMEM_BYTES>>>(gx, w_hh_l0, xlen, h0);

    // layer 1: K=512
    k_gemm<<<dim3(8, 128), 256>>>(h0, w_ih_l1,            b_ih_l1,      b_hh_l1,      gx,       512, NG);
    k_gemm<<<dim3(8, 128), 256>>>(h0, w_ih_l1 + NG * 512, b_ih_l1 + NG, b_hh_l1 + NG, gx + GXD, 512, NG);
    k_recur<<<dim3(8, 16), 256, RSMEM_BYTES>>>(gx, w_hh_l1, xlen, h1);

    k_emis<<<512, 256>>>(h1, dw, db, out);

    float* tags   = out + (size_t)Bsz * Ssz * Lsz;
    float* scores = tags + (size_t)Bsz * Ssz;
    k_viterbi<<<Bsz, 32>>>(out, xlen, trans, strn, etrn, tags, scores);
}

// round 6
// speedup vs baseline: 1.7814x; 1.7814x over previous
#include <cuda_runtime.h>
#include <math.h>

#define Bsz 32
#define Ssz 512
#define Esz 256
#define HDz 256
#define Hsz 512
#define Lsz 32
#define NG  1024   // 4*HD gate rows per direction

// ------------------- scratch -------------------
__device__ float g_x0[Bsz * Ssz * Esz];                 // embed out
__device__ float g_gx[2 * Bsz * Ssz * NG];              // gate preacts, both dirs
__device__ float g_h0[Bsz * Ssz * Hsz];                 // layer0 out
__device__ float g_h1[Bsz * Ssz * Hsz];                 // layer1 out

// ------------------- packed f32x2 helpers -------------------
__device__ __forceinline__ void dfma2(unsigned long long& d, unsigned long long a,
                                      unsigned long long b) {
    asm("fma.rn.f32x2 %0, %1, %2, %0;" : "+l"(d) : "l"(a), "l"(b));
}
__device__ __forceinline__ float2 up2(unsigned long long v) {
    float2 f;
    asm("mov.b64 {%0, %1}, %2;" : "=f"(f.x), "=f"(f.y) : "l"(v));
    return f;
}
__device__ __forceinline__ unsigned long long dupf(float b) {
    unsigned long long r;
    asm("mov.b64 %0, {%1, %1};" : "=l"(r) : "f"(b));
    return r;
}
__device__ __forceinline__ unsigned smem_u32(const void* p) {
    unsigned a;
    asm("{ .reg .u64 t; cvta.to.shared.u64 t, %1; cvt.u32.u64 %0, t; }"
        : "=r"(a) : "l"(p));
    return a;
}
__device__ __forceinline__ unsigned mapa32(unsigned addr, unsigned rank) {
    unsigned r;
    asm("mapa.shared::cluster.u32 %0, %1, %2;" : "=r"(r) : "r"(addr), "r"(rank));
    return r;
}
__device__ __forceinline__ void wait_par_acq_cluster(unsigned mbar, unsigned parity) {
    asm volatile(
        "{\n\t.reg .pred P;\n"
        "W%=:\n\t"
        "mbarrier.try_wait.parity.acquire.cluster.shared::cta.b64 P, [%0], %1, 0x989680;\n\t"
        "@P bra D%=;\n\t"
        "bra W%=;\n"
        "D%=:\n\t}"
        :: "r"(mbar), "r"(parity) : "memory");
}
__device__ __forceinline__ void st_async_f32(unsigned dst, float v, unsigned mbar) {
    asm volatile(
        "st.async.shared::cluster.mbarrier::complete_tx::bytes.b32 [%0], %1, [%2];"
        :: "r"(dst), "r"(__float_as_uint(v)), "r"(mbar) : "memory");
}

// ------------------- embed -------------------
__global__ void k_embed(const int* __restrict__ x, const float* __restrict__ emb,
                        float* __restrict__ out) {
    int row = blockIdx.x;
    int t = threadIdx.x;               // 64 threads
    int tok = x[row];
    const float4* s = (const float4*)(emb + (size_t)tok * Esz);
    ((float4*)(out + (size_t)row * Esz))[t] = s[t];
}

// ------------------- GEMM: C[M,N] = A[M,K] @ W[N,K]^T + b1 + b2 -------------------
__global__ __launch_bounds__(256) void k_gemm(const float* __restrict__ A,
                                              const float* __restrict__ W,
                                              const float* __restrict__ b1,
                                              const float* __restrict__ b2,
                                              float* __restrict__ C,
                                              int K, int N) {
    __shared__ __align__(16) float As[8][132];
    __shared__ __align__(16) float Bs[8][132];
    int m0 = blockIdx.y * 128, n0 = blockIdx.x * 128;
    int tid = threadIdx.x;
    int tx = tid & 15, ty = tid >> 4;
    int lr = tid >> 1;
    int lk = (tid & 1) * 4;
    const float* Ap = A + (size_t)(m0 + lr) * K + lk;
    const float* Wp = W + (size_t)(n0 + lr) * K + lk;

    unsigned long long acc[4][8];
#pragma unroll
    for (int i = 0; i < 4; i++)
#pragma unroll
        for (int j = 0; j < 8; j++) acc[i][j] = 0ull;

    float4 av = *(const float4*)(Ap);
    float4 bv = *(const float4*)(Wp);

    for (int k0 = 0; k0 < K; k0 += 8) {
        __syncthreads();
        As[lk + 0][lr] = av.x; As[lk + 1][lr] = av.y;
        As[lk + 2][lr] = av.z; As[lk + 3][lr] = av.w;
        Bs[lk + 0][lr] = bv.x; Bs[lk + 1][lr] = bv.y;
        Bs[lk + 2][lr] = bv.z; Bs[lk + 3][lr] = bv.w;
        __syncthreads();
        float4 av_n = av, bv_n = bv;
        if (k0 + 8 < K) {
            av_n = *(const float4*)(Ap + k0 + 8);
            bv_n = *(const float4*)(Wp + k0 + 8);
        }
#pragma unroll
        for (int kk = 0; kk < 8; kk++) {
            ulonglong2 A0 = *(const ulonglong2*)&As[kk][ty * 4];
            ulonglong2 A1 = *(const ulonglong2*)&As[kk][64 + ty * 4];
            float4 q0 = *(const float4*)&Bs[kk][tx * 4];
            float4 q1 = *(const float4*)&Bs[kk][64 + tx * 4];
            unsigned long long am[4] = {A0.x, A0.y, A1.x, A1.y};
            unsigned long long bd[8] = {dupf(q0.x), dupf(q0.y), dupf(q0.z), dupf(q0.w),
                                        dupf(q1.x), dupf(q1.y), dupf(q1.z), dupf(q1.w)};
#pragma unroll
            for (int mp = 0; mp < 4; mp++)
#pragma unroll
                for (int j = 0; j < 8; j++) dfma2(acc[mp][j], am[mp], bd[j]);
        }
        av = av_n; bv = bv_n;
    }

#pragma unroll
    for (int mp = 0; mp < 4; mp++) {
        int r = m0 + ((mp < 2) ? ty * 4 + 2 * mp : 64 + ty * 4 + 2 * (mp - 2));
#pragma unroll
        for (int j = 0; j < 8; j++) {
            int c = n0 + ((j < 4) ? 4 * tx + j : 64 + 4 * tx + (j - 4));
            float2 f = up2(acc[mp][j]);
            float bb = b1[c] + b2[c];
            C[(size_t)r * N + c]       = f.x + bb;
            C[(size_t)(r + 1) * N + c] = f.y + bb;
        }
    }
}

__device__ __forceinline__ float sigm(float x) { return 1.f / (1.f + expf(-x)); }

// ------------------- BiLSTM recurrence: reg-resident W, broadcast h, DSMEM push ----
// grid (8, 16): x = unit-slice (cluster dim 8), y = dir*8 + bgroup. 256 threads.
// FMA thread (warp w, lane l): khalf = w&1, col c = (w>>1)*32 + l (c = ul*4+gate).
// Cell thread t<128: b = t&3, ul = t>>2.
__global__ __launch_bounds__(256, 1) __cluster_dims__(8, 1, 1)
void k_recur(const float* __restrict__ gx, const float* __restrict__ w_hh,
             const int* __restrict__ xlen, float* __restrict__ hout) {
    __shared__ __align__(16) float hbuf[2048];      // 2 slots x [b][256]
    __shared__ __align__(16) float red[8 * 132];    // [kh*4+b][col] pitch 132
    __shared__ __align__(8) unsigned long long mbars[2];

    unsigned mb_full = smem_u32(mbars);
    unsigned hb_u32  = smem_u32(hbuf);

    int us  = blockIdx.x;
    int dir = blockIdx.y >> 3;
    int bg  = blockIdx.y & 7;
    int U0 = us * 32, B0 = bg * 4;
    int t = threadIdx.x;
    int w = t >> 5, l = t & 31;
    int kh = w & 1;
    int c  = (w >> 1) * 32 + l;
    int kbase = kh * 128;

    const float* wd  = w_hh + (size_t)dir * NG * HDz;
    const float* gxd = gx + (size_t)dir * ((size_t)Bsz * Ssz * NG);

    if (t == 0) {
        asm volatile("mbarrier.init.shared.b64 [%0], 1;" :: "r"(mb_full) : "memory");
        asm volatile("mbarrier.init.shared.b64 [%0], 1;" :: "r"(mb_full + 8) : "memory");
    }
    for (int idx = t; idx < 1024; idx += 256) hbuf[idx] = 0.f;

    // W slice into registers: wreg[j] = packed {w[c][kbase+2j], w[c][kbase+2j+1]}
    unsigned long long wreg[64];
    {
        int gr = (c & 3) * 256 + U0 + (c >> 2);
        const unsigned long long* wrow =
            (const unsigned long long*)(wd + (size_t)gr * HDz + kbase);
#pragma unroll
        for (int j = 0; j < 64; j++) wreg[j] = wrow[j];
    }

    // cell-thread state
    int cb = t & 3, cul = t >> 2;          // valid for t<128
    int clen = (t < 128) ? xlen[B0 + cb] : 0;
    float cst = 0.f, hst = 0.f;

    __syncthreads();
    asm volatile("barrier.cluster.arrive.aligned;" ::: "memory");
    asm volatile("barrier.cluster.wait.aligned;" ::: "memory");

    unsigned peer_hb[8], peer_full[8];
#pragma unroll
    for (int r = 0; r < 8; r++) {
        peer_hb[r]   = mapa32(hb_u32, r);
        peer_full[r] = mapa32(mb_full, r);
    }

    int u0cnt = 0, u1cnt = 0;

    for (int step = 0; step < 512; step++) {
        int si = step & 1;
        int so = si ^ 1;

        if (step >= 1) {
            int par;
            if (si) { par = u1cnt & 1; u1cnt++; }
            else    { par = u0cnt & 1; u0cnt++; }
            wait_par_acq_cluster(mb_full + si * 8, (unsigned)par);
        }
        if (step <= 510 && t == 0) {
            asm volatile(
                "mbarrier.arrive.expect_tx.release.cluster.shared::cta.b64 _, [%0], %1;"
                :: "r"(mb_full + so * 8), "r"(4096u) : "memory");
        }

        // prefetch gx for cell threads (consumed after FMA loop)
        float gxi = 0.f, gxf = 0.f, gxg = 0.f, gxo = 0.f;
        if (t < 128) {
            int s_b = step;
            if (dir) s_b = (step < clen) ? (clen - 1 - step) : step;
            const float* gp = gxd + ((size_t)(B0 + cb) * Ssz + s_b) * NG + U0 + cul;
            gxi = __ldg(gp);
            gxf = __ldg(gp + 256);
            gxg = __ldg(gp + 512);
            gxo = __ldg(gp + 768);
        }

        // FMA: acc_b = sum_k w[c][k] * h[b][k], k in [kbase, kbase+128)
        const float* hb = hbuf + si * 1024 + kbase;
        unsigned long long a0 = 0, a1 = 0, a2 = 0, a3 = 0;
#pragma unroll
        for (int kq = 0; kq < 32; kq++) {
            ulonglong2 h0 = *(const ulonglong2*)(hb + 4 * kq);
            ulonglong2 h1 = *(const ulonglong2*)(hb + 256 + 4 * kq);
            ulonglong2 h2 = *(const ulonglong2*)(hb + 512 + 4 * kq);
            ulonglong2 h3 = *(const ulonglong2*)(hb + 768 + 4 * kq);
            dfma2(a0, wreg[2 * kq], h0.x); dfma2(a0, wreg[2 * kq + 1], h0.y);
            dfma2(a1, wreg[2 * kq], h1.x); dfma2(a1, wreg[2 * kq + 1], h1.y);
            dfma2(a2, wreg[2 * kq], h2.x); dfma2(a2, wreg[2 * kq + 1], h2.y);
            dfma2(a3, wreg[2 * kq], h3.x); dfma2(a3, wreg[2 * kq + 1], h3.y);
        }
        float2 f;
        f = up2(a0); red[(kh * 4 + 0) * 132 + c] = f.x + f.y;
        f = up2(a1); red[(kh * 4 + 1) * 132 + c] = f.x + f.y;
        f = up2(a2); red[(kh * 4 + 2) * 132 + c] = f.x + f.y;
        f = up2(a3); red[(kh * 4 + 3) * 132 + c] = f.x + f.y;
        __syncthreads();

        if (t < 128) {
            int ci = cul * 4;
            float gi = red[cb * 132 + ci]     + red[(4 + cb) * 132 + ci]     + gxi;
            float gf = red[cb * 132 + ci + 1] + red[(4 + cb) * 132 + ci + 1] + gxf;
            float gg = red[cb * 132 + ci + 2] + red[(4 + cb) * 132 + ci + 2] + gxg;
            float go = red[cb * 132 + ci + 3] + red[(4 + cb) * 132 + ci + 3] + gxo;

            float iv = sigm(gi), fv = sigm(gf), gv = tanhf(gg), ov = sigm(go);
            float cn = fv * cst + iv * gv;
            float hn = ov * tanhf(cn);
            bool m = step < clen;
            cst = m ? cn : cst;
            hst = m ? hn : hst;
            float outv = m ? hn : 0.f;

            if (step <= 510) {
                unsigned off = (unsigned)((so << 10) + cb * 256 + U0 + cul) * 4u;
#pragma unroll
                for (int r = 0; r < 8; r++)
                    st_async_f32(peer_hb[r] + off, hst, peer_full[r] + so * 8);
            }

            int pos, oc;
            if (!dir) { pos = step; oc = U0 + cul; }
            else {
                pos = m ? (clen - 1 - step) : step;
                oc = 256 + U0 + cul;
            }
            hout[((size_t)(B0 + cb) * Ssz + pos) * Hsz + oc] = outv;
        }
        // no trailing sync needed: next-phase writes are gated by the full-mbar,
        // which can only complete after every cell thread issued its sends
        // (which follow its red reads in program order).
    }
}

// ------------------- emissions: out[M,32] = h[M,512] @ dw[32,512]^T + db -------------------
__global__ __launch_bounds__(256) void k_emis(const float* __restrict__ h,
                                              const float* __restrict__ dw,
                                              const float* __restrict__ db,
                                              float* __restrict__ out) {
    __shared__ float wT[128 * 33];
    __shared__ float hs[32 * 128];
    int tid = threadIdx.x;
    int w = tid >> 5, j = tid & 31;
    int row0 = blockIdx.x * 32;
    float acc[4] = {0.f, 0.f, 0.f, 0.f};
    for (int kc = 0; kc < 4; kc++) {
        __syncthreads();
        for (int idx = tid; idx < 4096; idx += 256) {
            int jj = idx >> 7, k = idx & 127;
            wT[k * 33 + jj] = dw[(size_t)jj * 512 + kc * 128 + k];
        }
        for (int idx = tid; idx < 4096; idx += 256) {
            int r = idx >> 7, k = idx & 127;
            hs[r * 128 + k] = h[(size_t)(row0 + r) * 512 + kc * 128 + k];
        }
        __syncthreads();
#pragma unroll 4
        for (int k = 0; k < 128; k++) {
            float wv = wT[k * 33 + j];
#pragma unroll
            for (int i = 0; i < 4; i++) acc[i] += hs[(w * 4 + i) * 128 + k] * wv;
        }
    }
    float bias = db[j];
#pragma unroll
    for (int i = 0; i < 4; i++)
        out[(size_t)(row0 + w * 4 + i) * 32 + j] = acc[i] + bias;
}

// ------------------- Viterbi: 32 blocks x 32 threads -------------------
__global__ void k_viterbi(const float* __restrict__ em, const int* __restrict__ xlen,
                          const float* __restrict__ trans, const float* __restrict__ st,
                          const float* __restrict__ et,
                          float* __restrict__ tags_out, float* __restrict__ scores_out) {
    __shared__ unsigned char bp[512][32];
    int b = blockIdx.x, j = threadIdx.x;
    int len = xlen[b];
    float tc[32];
#pragma unroll
    for (int i = 0; i < 32; i++) tc[i] = trans[i * 32 + j];
    const float* e = em + (size_t)b * Ssz * Lsz;
    float alpha = st[j] + e[j];
    for (int t = 1; t < 512; t++) {
        if (t < len) {
            float best = -1e30f; int arg = 0;
#pragma unroll
            for (int i = 0; i < 32; i++) {
                float ai = __shfl_sync(0xffffffffu, alpha, i);
                float cand = ai + tc[i];
                if (cand > best) { best = cand; arg = i; }
            }
            alpha = best + e[(size_t)t * 32 + j];
            bp[t][j] = (unsigned char)arg;
        } else {
            bp[t][j] = (unsigned char)j;
        }
    }
    __syncwarp();
    float fin = alpha + et[j];
    float bv = fin; int bi = j;
#pragma unroll
    for (int off = 16; off; off >>= 1) {
        float ovv = __shfl_down_sync(0xffffffffu, bv, off);
        int oi = __shfl_down_sync(0xffffffffu, bi, off);
        if (ovv > bv || (ovv == bv && oi < bi)) { bv = ovv; bi = oi; }
    }
    if (j == 0) {
        scores_out[b] = bv;
        int tg = bi;
        for (int t = 511; t >= 1; t--) {
            tags_out[(size_t)b * Ssz + t] = (t < len) ? (float)tg : 0.f;
            tg = bp[t][tg];
        }
        tags_out[(size_t)b * Ssz] = (float)tg;
    }
}

// ------------------- launch -------------------
extern "C" void kernel_launch(void* const* d_in, const int* in_sizes, int n_in,
                              void* d_out, int out_size) {
    const int*   x       = (const int*)d_in[0];
    const int*   xlen    = (const int*)d_in[1];
    const float* emb     = (const float*)d_in[2];
    const float* w_ih_l0 = (const float*)d_in[3];
    const float* w_hh_l0 = (const float*)d_in[4];
    const float* b_ih_l0 = (const float*)d_in[5];
    const float* b_hh_l0 = (const float*)d_in[6];
    const float* w_ih_l1 = (const float*)d_in[7];
    const float* w_hh_l1 = (const float*)d_in[8];
    const float* b_ih_l1 = (const float*)d_in[9];
    const float* b_hh_l1 = (const float*)d_in[10];
    const float* dw      = (const float*)d_in[11];
    const float* db      = (const float*)d_in[12];
    const float* trans   = (const float*)d_in[13];
    const float* strn    = (const float*)d_in[14];
    const float* etrn    = (const float*)d_in[15];
    float* out = (float*)d_out;

    float *x0, *gx, *h0, *h1;
    cudaGetSymbolAddress((void**)&x0, g_x0);
    cudaGetSymbolAddress((void**)&gx, g_gx);
    cudaGetSymbolAddress((void**)&h0, g_h0);
    cudaGetSymbolAddress((void**)&h1, g_h1);

    const size_t GXD = (size_t)Bsz * Ssz * NG;

    k_embed<<<Bsz * Ssz, 64>>>(x, emb, x0);

    // layer 0: K=256
    k_gemm<<<dim3(8, 128), 256>>>(x0, w_ih_l0,            b_ih_l0,      b_hh_l0,      gx,       256, NG);
    k_gemm<<<dim3(8, 128), 256>>>(x0, w_ih_l0 + NG * 256, b_ih_l0 + NG, b_hh_l0 + NG, gx + GXD, 256, NG);
    k_recur<<<dim3(8, 16), 256>>>(gx, w_hh_l0, xlen, h0);

    // layer 1: K=512
    k_gemm<<<dim3(8, 128), 256>>>(h0, w_ih_l1,            b_ih_l1,      b_hh_l1,      gx,       512, NG);
    k_gemm<<<dim3(8, 128), 256>>>(h0, w_ih_l1 + NG * 512, b_ih_l1 + NG, b_hh_l1 + NG, gx + GXD, 512, NG);
    k_recur<<<dim3(8, 16), 256>>>(gx, w_hh_l1, xlen, h1);

    k_emis<<<512, 256>>>(h1, dw, db, out);

    float* tags   = out + (size_t)Bsz * Ssz * Lsz;
    float* scores = tags + (size_t)Bsz * Ssz;
    k_viterbi<<<Bsz, 32>>>(out, xlen, trans, strn, etrn, tags, scores);
}